// round 13
// baseline (speedup 1.0000x reference)
#include <cuda_runtime.h>
#include <cuda_bf16.h>
#include <math.h>

// Problem constants
#define BATCH 128
#define NNODE 1024
#define RTOT  (BATCH * NNODE)   // 131072
#define EEDGE 4096
#define HID   128

#define ROWS_PER_BLK 16
#define XS 68                   // token-stride: 4*XS % 32 == 16 -> 2-way bank spread

// ---------------- scratch (__device__ globals; no allocation allowed) ----------------
__device__ float g_xl[(size_t)RTOT * HID];
__device__ float g_xr[(size_t)RTOT * HID];
__device__ __align__(16) float g_qkvt[3 * 40 * 128];   // [l][k][n] n<120 valid, pad 0
__device__ __align__(16) float g_wot [3 * 40 * 64];    // [l][k][n] n<40 valid, pad 0
__device__ __align__(16) float g_w1t [3 * 40 * 256];   // [l][k][n]
__device__ __align__(16) float g_w2t [3 * 256 * 64];   // [l][k][n] n<40 valid, pad 0
__device__ __align__(16) float g_e1t [192 * 128];      // [k][n]
__device__ __align__(16) float g_e2t [128 * 128];
__device__ __align__(16) float g_wlt [128 * 128];
__device__ __align__(16) float g_wrt [128 * 128];
__device__ int g_csr_off[NNODE + 1];
__device__ int g_csr_src[EEDGE];

// ---------------- prep: transpose all weights to k-major (with padding) ----------------
__global__ void prep_kernel(const float* __restrict__ wqkv, const float* __restrict__ wo,
                            const float* __restrict__ w1,   const float* __restrict__ w2,
                            const float* __restrict__ We1,  const float* __restrict__ We2,
                            const float* __restrict__ wl,   const float* __restrict__ wr) {
    int i0 = blockIdx.x * blockDim.x + threadIdx.x;
    int stride = gridDim.x * blockDim.x;
    for (int i = i0; i < 3 * 40 * 128; i += stride) {
        int n = i & 127, k = (i >> 7) % 40, l = i / (40 * 128);
        g_qkvt[i] = (n < 120) ? __ldg(wqkv + l * 4800 + n * 40 + k) : 0.f;
    }
    for (int i = i0; i < 3 * 40 * 64; i += stride) {
        int n = i & 63, k = (i >> 6) % 40, l = i / 2560;
        g_wot[i] = (n < 40) ? __ldg(wo + l * 1600 + n * 40 + k) : 0.f;
    }
    for (int i = i0; i < 3 * 40 * 256; i += stride) {
        int n = i & 255, k = (i >> 8) % 40, l = i / 10240;
        g_w1t[i] = __ldg(w1 + l * 10240 + n * 40 + k);
    }
    for (int i = i0; i < 3 * 256 * 64; i += stride) {
        int n = i & 63, k = (i >> 6) % 256, l = i / 16384;
        g_w2t[i] = (n < 40) ? __ldg(w2 + l * 10240 + n * 256 + k) : 0.f;
    }
    for (int i = i0; i < 192 * 128; i += stride) {
        int n = i & 127, k = i >> 7;
        g_e1t[i] = __ldg(We1 + n * 192 + k);
    }
    for (int i = i0; i < 128 * 128; i += stride) {
        int n = i & 127, k = i >> 7;
        g_e2t[i] = __ldg(We2 + n * 128 + k);
        g_wlt[i] = __ldg(wl + n * 128 + k);
        g_wrt[i] = __ldg(wr + n * 128 + k);
    }
}

// ---------------- CSR build (single block, deterministic) ----------------
__global__ void csr_build_kernel(const int* __restrict__ edge_index) {
    __shared__ int cnt[NNODE];
    __shared__ int off[NNODE + 1];
    __shared__ int cur[NNODE];
    int t = threadIdx.x;
    cnt[t] = 0;
    __syncthreads();
    for (int e = t; e < EEDGE; e += 1024) atomicAdd(&cnt[edge_index[EEDGE + e]], 1);
    __syncthreads();
    if (t == 0) {
        off[0] = 0;
        for (int i = 0; i < NNODE; ++i) off[i + 1] = off[i] + cnt[i];
    }
    __syncthreads();
    cur[t] = off[t];
    __syncthreads();
    for (int e = t; e < EEDGE; e += 1024) {
        int pos = atomicAdd(&cur[edge_index[EEDGE + e]], 1);
        g_csr_src[pos] = edge_index[e];
    }
    g_csr_off[t] = off[t];
    if (t == 0) g_csr_off[NNODE] = off[NNODE];
    __syncthreads();
    int lo = off[t], hi = off[t + 1];
    for (int i = lo + 1; i < hi; ++i) {
        int v = g_csr_src[i];
        int j = i - 1;
        while (j >= lo && g_csr_src[j] > v) { g_csr_src[j + 1] = g_csr_src[j]; --j; }
        g_csr_src[j + 1] = v;
    }
}

// ---------------- fused transformer + emb + xl/xr (8x8 / 4x8 tiles, f4 C-stores) ----------------
// 128 threads. smem: XA[40][68] | QK[128][68] | WB[5120]
#define SMEM_FLOATS 16544
#define SMEM_BYTES  (SMEM_FLOATS * 4)

__global__ __launch_bounds__(128, 3) void tf_kernel(
    int base,
    const float* __restrict__ obs, const float* __restrict__ pe,
    const float* __restrict__ bqkv_all, const float* __restrict__ bo_all,
    const float* __restrict__ b1_all,   const float* __restrict__ b2_all,
    const float* __restrict__ ln1g_all, const float* __restrict__ ln1b_all,
    const float* __restrict__ ln2g_all, const float* __restrict__ ln2b_all,
    const float* __restrict__ bemb1, const float* __restrict__ bemb2,
    const float* __restrict__ gbl,   const float* __restrict__ gbr)
{
    extern __shared__ float dsm[];
    float* XA = dsm;                    // 40*68 = 2720
    float* QK = dsm + 2720;             // 128*68 = 8704
    float* WB = dsm + 11424;            // 5120

    const int tid = threadIdx.x;
    const int rbase = (base + blockIdx.x) * ROWS_PER_BLK;
    const int mg8 = tid >> 4, ng16 = tid & 15;
    const int mg16 = tid >> 3, ng8 = tid & 7;

    // ---- load X = obs(token) + pe, token-major: XA[d][tok], tok = 4*rr + t ----
    for (int i = tid; i < 2560; i += 128) {
        int rr = i / 160, off = i % 160;
        int t = off / 40, d = off % 40;
        XA[d * XS + 4 * rr + t] =
            __ldg(obs + (size_t)(rbase + rr) * 200 + off) + __ldg(pe + off);
    }
    __syncthreads();

    for (int L = 0; L < 3; ++L) {
        // ======== QKV: C[64,128] single pass, 8x8 tiles ========
        for (int i = tid; i < 1280; i += 128)
            ((float4*)WB)[i] = __ldg((const float4*)(g_qkvt + L * 5120) + i);
        __syncthreads();
        {
            float acc[8][8];
#pragma unroll
            for (int j = 0; j < 8; ++j) {
                int out = (j < 4) ? 4 * ng16 + j : 64 + 4 * ng16 + j - 4;
                float bv = (out < 120) ? __ldg(bqkv_all + L * 120 + out) : 0.f;
#pragma unroll
                for (int i = 0; i < 8; ++i) acc[i][j] = bv;
            }
#pragma unroll 4
            for (int k = 0; k < 40; ++k) {
                float4 a0 = *(const float4*)(XA + k * XS + 8 * mg8);
                float4 a1 = *(const float4*)(XA + k * XS + 8 * mg8 + 4);
                float4 b0 = *(const float4*)(WB + k * 128 + 4 * ng16);
                float4 b1 = *(const float4*)(WB + k * 128 + 64 + 4 * ng16);
                float av[8] = {a0.x, a0.y, a0.z, a0.w, a1.x, a1.y, a1.z, a1.w};
                float bw[8] = {b0.x, b0.y, b0.z, b0.w, b1.x, b1.y, b1.z, b1.w};
#pragma unroll
                for (int i = 0; i < 8; ++i)
#pragma unroll
                    for (int j = 0; j < 8; ++j) acc[i][j] += av[i] * bw[j];
            }
#pragma unroll
            for (int j = 0; j < 8; ++j) {
                int out = (j < 4) ? 4 * ng16 + j : 64 + 4 * ng16 + j - 4;
                float4 v0 = make_float4(acc[0][j], acc[1][j], acc[2][j], acc[3][j]);
                float4 v1 = make_float4(acc[4][j], acc[5][j], acc[6][j], acc[7][j]);
                *(float4*)(QK + out * XS + 8 * mg8)     = v0;
                *(float4*)(QK + out * XS + 8 * mg8 + 4) = v1;
            }
        }
        __syncthreads();

        // ======== attention: 2 threads/token; O overwrites Q rows 0..39 ========
        {
            int tok = tid >> 1, hh = tid & 1;
            int t = tok & 3, tb = tok & ~3;
            float q[20];
#pragma unroll
            for (int d = 0; d < 20; ++d) q[d] = QK[(hh * 20 + d) * XS + tok];
            float sc[4], mx = -1e30f;
            for (int j = 0; j <= t; ++j) {
                float s = 0.f;
#pragma unroll
                for (int d = 0; d < 20; ++d) s += q[d] * QK[(40 + hh * 20 + d) * XS + tb + j];
                sc[j] = s * 0.22360679774997896f;
                mx = fmaxf(mx, sc[j]);
            }
            float den = 0.f;
            for (int j = 0; j <= t; ++j) { sc[j] = __expf(sc[j] - mx); den += sc[j]; }
            float iden = 1.f / den;
            float o[20];
#pragma unroll
            for (int d = 0; d < 20; ++d) {
                float a = 0.f;
                for (int j = 0; j <= t; ++j) a += sc[j] * QK[(80 + hh * 20 + d) * XS + tb + j];
                o[d] = a * iden;
            }
#pragma unroll
            for (int d = 0; d < 20; ++d) QK[(hh * 20 + d) * XS + tok] = o[d];
        }
        __syncthreads();

        // ======== WO: C[64,64pad], 4x8 tiles; Y -> QK rows 40..103 ========
        for (int i = tid; i < 640; i += 128)
            ((float4*)WB)[i] = __ldg((const float4*)(g_wot + L * 2560) + i);
        __syncthreads();
        {
            float cw[4][8];
#pragma unroll
            for (int j = 0; j < 8; ++j) {
                int out = (j < 4) ? 4 * ng8 + j : 32 + 4 * ng8 + j - 4;
                float bv = (out < 40) ? __ldg(bo_all + L * 40 + out) : 0.f;
                if (out < 40) {
                    float4 xv = *(const float4*)(XA + out * XS + 4 * mg16);
                    cw[0][j] = bv + xv.x; cw[1][j] = bv + xv.y;
                    cw[2][j] = bv + xv.z; cw[3][j] = bv + xv.w;
                } else {
#pragma unroll
                    for (int i = 0; i < 4; ++i) cw[i][j] = bv;
                }
            }
#pragma unroll 4
            for (int k = 0; k < 40; ++k) {
                float4 a = *(const float4*)(QK + k * XS + 4 * mg16);
                float4 b0 = *(const float4*)(WB + k * 64 + 4 * ng8);
                float4 b1 = *(const float4*)(WB + k * 64 + 32 + 4 * ng8);
                float av[4] = {a.x, a.y, a.z, a.w};
                float bw[8] = {b0.x, b0.y, b0.z, b0.w, b1.x, b1.y, b1.z, b1.w};
#pragma unroll
                for (int i = 0; i < 4; ++i)
#pragma unroll
                    for (int j = 0; j < 8; ++j) cw[i][j] += av[i] * bw[j];
            }
#pragma unroll
            for (int j = 0; j < 8; ++j) {
                int out = (j < 4) ? 4 * ng8 + j : 32 + 4 * ng8 + j - 4;
                float4 v = make_float4(cw[0][j], cw[1][j], cw[2][j], cw[3][j]);
                *(float4*)(QK + (40 + out) * XS + 4 * mg16) = v;
            }
        }
        __syncthreads();

        // ======== LN1: QK rows 40..79 -> XA ========
        {
            int tok = tid >> 1, half = tid & 1;
            float v[20], s = 0.f;
#pragma unroll
            for (int d = 0; d < 20; ++d) { v[d] = QK[(40 + half * 20 + d) * XS + tok]; s += v[d]; }
            s += __shfl_xor_sync(0xffffffffu, s, 1);
            float mean = s * 0.025f;
            float vs = 0.f;
#pragma unroll
            for (int d = 0; d < 20; ++d) { float dv = v[d] - mean; vs += dv * dv; }
            vs += __shfl_xor_sync(0xffffffffu, vs, 1);
            float rstd = rsqrtf(vs * 0.025f + 1e-6f);
#pragma unroll
            for (int d = 0; d < 20; ++d) {
                int dd = half * 20 + d;
                XA[dd * XS + tok] = (v[d] - mean) * rstd * __ldg(ln1g_all + L * 40 + dd)
                                    + __ldg(ln1b_all + L * 40 + dd);
            }
        }
        __syncthreads();

        // ======== FFN: 2 chunks of 128 hidden; up 8x8, down 4x8 ========
        float y[4][8];
#pragma unroll
        for (int j = 0; j < 8; ++j) {
            int out = (j < 4) ? 4 * ng8 + j : 32 + 4 * ng8 + j - 4;
            float bv = (out < 40) ? __ldg(b2_all + L * 40 + out) : 0.f;
            if (out < 40) {
                float4 xv = *(const float4*)(XA + out * XS + 4 * mg16);
                y[0][j] = bv + xv.x; y[1][j] = bv + xv.y;
                y[2][j] = bv + xv.z; y[3][j] = bv + xv.w;
            } else {
#pragma unroll
                for (int i = 0; i < 4; ++i) y[i][j] = bv;
            }
        }
        for (int c = 0; c < 2; ++c) {
            // --- up: C[64,128] 8x8, relu -> QK rows 0..127 ---
            for (int i = tid; i < 1280; i += 128) {
                int k = i >> 5, n4 = i & 31;
                ((float4*)WB)[i] = __ldg((const float4*)(g_w1t + L * 10240 + k * 256 + 128 * c) + n4);
            }
            __syncthreads();
            {
                float au[8][8];
#pragma unroll
                for (int j = 0; j < 8; ++j) {
                    int out = (j < 4) ? 4 * ng16 + j : 64 + 4 * ng16 + j - 4;
                    float bv = __ldg(b1_all + L * 256 + 128 * c + out);
#pragma unroll
                    for (int i = 0; i < 8; ++i) au[i][j] = bv;
                }
#pragma unroll 4
                for (int k = 0; k < 40; ++k) {
                    float4 a0 = *(const float4*)(XA + k * XS + 8 * mg8);
                    float4 a1 = *(const float4*)(XA + k * XS + 8 * mg8 + 4);
                    float4 b0 = *(const float4*)(WB + k * 128 + 4 * ng16);
                    float4 b1 = *(const float4*)(WB + k * 128 + 64 + 4 * ng16);
                    float av[8] = {a0.x, a0.y, a0.z, a0.w, a1.x, a1.y, a1.z, a1.w};
                    float bw[8] = {b0.x, b0.y, b0.z, b0.w, b1.x, b1.y, b1.z, b1.w};
#pragma unroll
                    for (int i = 0; i < 8; ++i)
#pragma unroll
                        for (int j = 0; j < 8; ++j) au[i][j] += av[i] * bw[j];
                }
#pragma unroll
                for (int j = 0; j < 8; ++j) {
                    int out = (j < 4) ? 4 * ng16 + j : 64 + 4 * ng16 + j - 4;
                    float4 v0 = make_float4(fmaxf(au[0][j], 0.f), fmaxf(au[1][j], 0.f),
                                            fmaxf(au[2][j], 0.f), fmaxf(au[3][j], 0.f));
                    float4 v1 = make_float4(fmaxf(au[4][j], 0.f), fmaxf(au[5][j], 0.f),
                                            fmaxf(au[6][j], 0.f), fmaxf(au[7][j], 0.f));
                    *(float4*)(QK + out * XS + 8 * mg8)     = v0;
                    *(float4*)(QK + out * XS + 8 * mg8 + 4) = v1;
                }
            }
            // --- down: 2 sub-chunks of k=64, 4x8 into y regs ---
            for (int sk = 0; sk < 2; ++sk) {
                __syncthreads();
                for (int i = tid; i < 1024; i += 128)
                    ((float4*)WB)[i] = __ldg((const float4*)(g_w2t + L * 16384 + (128 * c + 64 * sk) * 64) + i);
                __syncthreads();
#pragma unroll 4
                for (int k = 0; k < 64; ++k) {
                    float4 a = *(const float4*)(QK + (64 * sk + k) * XS + 4 * mg16);
                    float4 b0 = *(const float4*)(WB + k * 64 + 4 * ng8);
                    float4 b1 = *(const float4*)(WB + k * 64 + 32 + 4 * ng8);
                    float av[4] = {a.x, a.y, a.z, a.w};
                    float bw[8] = {b0.x, b0.y, b0.z, b0.w, b1.x, b1.y, b1.z, b1.w};
#pragma unroll
                    for (int i = 0; i < 4; ++i)
#pragma unroll
                        for (int j = 0; j < 8; ++j) y[i][j] += av[i] * bw[j];
                }
                __syncthreads();
            }
        }
        // write Y -> QK rows 0..63
#pragma unroll
        for (int j = 0; j < 8; ++j) {
            int out = (j < 4) ? 4 * ng8 + j : 32 + 4 * ng8 + j - 4;
            float4 v = make_float4(y[0][j], y[1][j], y[2][j], y[3][j]);
            *(float4*)(QK + out * XS + 4 * mg16) = v;
        }
        __syncthreads();

        // ======== LN2: QK rows 0..39 -> XA ========
        {
            int tok = tid >> 1, half = tid & 1;
            float v[20], s = 0.f;
#pragma unroll
            for (int d = 0; d < 20; ++d) { v[d] = QK[(half * 20 + d) * XS + tok]; s += v[d]; }
            s += __shfl_xor_sync(0xffffffffu, s, 1);
            float mean = s * 0.025f;
            float vs = 0.f;
#pragma unroll
            for (int d = 0; d < 20; ++d) { float dv = v[d] - mean; vs += dv * dv; }
            vs += __shfl_xor_sync(0xffffffffu, vs, 1);
            float rstd = rsqrtf(vs * 0.025f + 1e-6f);
#pragma unroll
            for (int d = 0; d < 20; ++d) {
                int dd = half * 20 + d;
                XA[dd * XS + tok] = (v[d] - mean) * rstd * __ldg(ln2g_all + L * 40 + dd)
                                    + __ldg(ln2b_all + L * 40 + dd);
            }
        }
        __syncthreads();
    }

    // ======== tail: ret -> emb1 -> emb2 -> xl/xr (M=16 rows) ========
    float* RT  = QK;            // [192][20] = 3840
    float* E1T = QK + 3840;     // [128][20] = 2560
    float* E2T = XA;            // [128][20] = 2560 (<= 2720)
    for (int i = tid; i < 3072; i += 128) {
        int k = i / 16, rr = i % 16;
        float v;
        if (k < 160) { int t = k / 40, d = k % 40; v = XA[d * XS + 4 * rr + t]; }
        else v = __ldg(obs + (size_t)(rbase + rr) * 200 + 160 + (k - 160));
        RT[k * 20 + rr] = v;
    }
    __syncthreads();

    const int mg4 = tid >> 5, ng32 = tid & 31;
    float tc[4][4];

    // ---- emb1: C[16,128] = RT·We1ᵀ, k=192 in 12 chunks of 16 ----
#pragma unroll
    for (int j = 0; j < 4; ++j) {
        float bv = __ldg(bemb1 + 4 * ng32 + j);
#pragma unroll
        for (int i = 0; i < 4; ++i) tc[i][j] = bv;
    }
    for (int kc = 0; kc < 192; kc += 16) {
        for (int i = tid; i < 512; i += 128)
            ((float4*)WB)[i] = __ldg((const float4*)(g_e1t + kc * 128) + i);
        __syncthreads();
#pragma unroll
        for (int kk = 0; kk < 16; ++kk) {
            float4 a = *(const float4*)(RT + (kc + kk) * 20 + 4 * mg4);
            float4 b = *(const float4*)(WB + kk * 128 + 4 * ng32);
            float av[4] = {a.x, a.y, a.z, a.w};
#pragma unroll
            for (int i = 0; i < 4; ++i) {
                tc[i][0] += av[i] * b.x; tc[i][1] += av[i] * b.y;
                tc[i][2] += av[i] * b.z; tc[i][3] += av[i] * b.w;
            }
        }
        __syncthreads();
    }
#pragma unroll
    for (int j = 0; j < 4; ++j) {
        float4 v = make_float4(fmaxf(tc[0][j], 0.f), fmaxf(tc[1][j], 0.f),
                               fmaxf(tc[2][j], 0.f), fmaxf(tc[3][j], 0.f));
        *(float4*)(E1T + (4 * ng32 + j) * 20 + 4 * mg4) = v;
    }
    __syncthreads();

    // ---- emb2: C[16,128] = E1T·We2ᵀ, k=128 in 8 chunks ----
#pragma unroll
    for (int j = 0; j < 4; ++j) {
        float bv = __ldg(bemb2 + 4 * ng32 + j);
#pragma unroll
        for (int i = 0; i < 4; ++i) tc[i][j] = bv;
    }
    for (int kc = 0; kc < 128; kc += 16) {
        for (int i = tid; i < 512; i += 128)
            ((float4*)WB)[i] = __ldg((const float4*)(g_e2t + kc * 128) + i);
        __syncthreads();
#pragma unroll
        for (int kk = 0; kk < 16; ++kk) {
            float4 a = *(const float4*)(E1T + (kc + kk) * 20 + 4 * mg4);
            float4 b = *(const float4*)(WB + kk * 128 + 4 * ng32);
            float av[4] = {a.x, a.y, a.z, a.w};
#pragma unroll
            for (int i = 0; i < 4; ++i) {
                tc[i][0] += av[i] * b.x; tc[i][1] += av[i] * b.y;
                tc[i][2] += av[i] * b.z; tc[i][3] += av[i] * b.w;
            }
        }
        __syncthreads();
    }
#pragma unroll
    for (int j = 0; j < 4; ++j) {
        float4 v = make_float4(fmaxf(tc[0][j], 0.f), fmaxf(tc[1][j], 0.f),
                               fmaxf(tc[2][j], 0.f), fmaxf(tc[3][j], 0.f));
        *(float4*)(E2T + (4 * ng32 + j) * 20 + 4 * mg4) = v;
    }
    __syncthreads();

    // ---- xl then xr: C[16,128] = E2T·Wᵀ + bias -> global ----
    for (int m = 0; m < 2; ++m) {
        const float* wt = m ? g_wrt : g_wlt;
        const float* gb = m ? gbr : gbl;
        float* gout = m ? g_xr : g_xl;
#pragma unroll
        for (int j = 0; j < 4; ++j) {
            float bv = __ldg(gb + 4 * ng32 + j);
#pragma unroll
            for (int i = 0; i < 4; ++i) tc[i][j] = bv;
        }
        for (int kc = 0; kc < 128; kc += 16) {
            for (int i = tid; i < 512; i += 128)
                ((float4*)WB)[i] = __ldg((const float4*)(wt + kc * 128) + i);
            __syncthreads();
#pragma unroll
            for (int kk = 0; kk < 16; ++kk) {
                float4 a = *(const float4*)(E2T + (kc + kk) * 20 + 4 * mg4);
                float4 b = *(const float4*)(WB + kk * 128 + 4 * ng32);
                float av[4] = {a.x, a.y, a.z, a.w};
#pragma unroll
                for (int i = 0; i < 4; ++i) {
                    tc[i][0] += av[i] * b.x; tc[i][1] += av[i] * b.y;
                    tc[i][2] += av[i] * b.z; tc[i][3] += av[i] * b.w;
                }
            }
            __syncthreads();
        }
#pragma unroll
        for (int i = 0; i < 4; ++i) {
            float4 v = make_float4(tc[i][0], tc[i][1], tc[i][2], tc[i][3]);
            *(float4*)(gout + (size_t)(rbase + 4 * mg4 + i) * 128 + 4 * ng32) = v;
        }
    }
}

// ---------------- GAT gather + final linear (warp per row, online softmax) ----------------
__global__ void gat_kernel(const float* __restrict__ gat_att,
                           const float* __restrict__ gat_bias,
                           const float* __restrict__ Wq,
                           const float* __restrict__ bq,
                           float* __restrict__ out)
{
    const int warp = (blockIdx.x * blockDim.x + threadIdx.x) >> 5;
    const int lane = threadIdx.x & 31;
    if (warp >= RTOT) return;
    const int r = warp;
    const int b = r >> 10;
    const int n = r & 1023;

    float xrv[4], attv[4], m[4], l[4], acc[4];
#pragma unroll
    for (int hh = 0; hh < 4; ++hh) {
        xrv[hh]  = g_xr[(size_t)r * 128 + hh * 32 + lane];
        attv[hh] = __ldg(gat_att + hh * 32 + lane);
        m[hh] = -1e30f; l[hh] = 0.f; acc[hh] = 0.f;
    }
    const int lo = g_csr_off[n], hi = g_csr_off[n + 1];
    for (int it = -1; it < hi - lo; ++it) {
        const int srcn = (it < 0) ? n : g_csr_src[lo + it];
        const float* xlp = g_xl + ((size_t)(b * 1024 + srcn)) * 128;
        float xlv[4], ev[4];
#pragma unroll
        for (int hh = 0; hh < 4; ++hh) {
            xlv[hh] = xlp[hh * 32 + lane];
            float mm = xlv[hh] + xrv[hh];
            mm = (mm > 0.f) ? mm : 0.2f * mm;
            float p = mm * attv[hh];
#pragma unroll
            for (int s = 16; s > 0; s >>= 1) p += __shfl_xor_sync(0xffffffffu, p, s);
            ev[hh] = p;
        }
#pragma unroll
        for (int hh = 0; hh < 4; ++hh) {
            float nm  = fmaxf(m[hh], ev[hh]);
            float pe_ = expf(ev[hh] - nm);
            float sc  = expf(m[hh] - nm);
            l[hh]   = l[hh] * sc + pe_;
            acc[hh] = acc[hh] * sc + pe_ * xlv[hh];
            m[hh] = nm;
        }
    }
    float h2[4];
#pragma unroll
    for (int hh = 0; hh < 4; ++hh)
        h2[hh] = acc[hh] / l[hh] + __ldg(gat_bias + hh * 32 + lane);

#pragma unroll
    for (int a = 0; a < 8; ++a) {
        float p = 0.f;
#pragma unroll
        for (int hh = 0; hh < 4; ++hh)
            p += h2[hh] * __ldg(Wq + a * 128 + hh * 32 + lane);
#pragma unroll
        for (int s = 16; s > 0; s >>= 1) p += __shfl_xor_sync(0xffffffffu, p, s);
        if (lane == 0) out[(size_t)r * 8 + a] = p + __ldg(bq + a);
    }
}

// ---------------- launch ----------------
extern "C" void kernel_launch(void* const* d_in, const int* in_sizes, int n_in,
                              void* d_out, int out_size) {
    const float* obs      = (const float*)d_in[0];
    const int*   edge_idx = (const int*)  d_in[1];
    const float* W_emb1   = (const float*)d_in[2];
    const float* b_emb1   = (const float*)d_in[3];
    const float* W_emb2   = (const float*)d_in[4];
    const float* b_emb2   = (const float*)d_in[5];
    const float* tf_wqkv  = (const float*)d_in[6];
    const float* tf_bqkv  = (const float*)d_in[7];
    const float* tf_wo    = (const float*)d_in[8];
    const float* tf_bo    = (const float*)d_in[9];
    const float* ffn_w1   = (const float*)d_in[10];
    const float* ffn_b1   = (const float*)d_in[11];
    const float* ffn_w2   = (const float*)d_in[12];
    const float* ffn_b2   = (const float*)d_in[13];
    const float* ln1_g    = (const float*)d_in[14];
    const float* ln1_b    = (const float*)d_in[15];
    const float* ln2_g    = (const float*)d_in[16];
    const float* ln2_b    = (const float*)d_in[17];
    const float* gat_wl   = (const float*)d_in[18];
    const float* gat_bl   = (const float*)d_in[19];
    const float* gat_wr   = (const float*)d_in[20];
    const float* gat_br   = (const float*)d_in[21];
    const float* gat_att  = (const float*)d_in[22];
    const float* gat_bias = (const float*)d_in[23];
    const float* W_q      = (const float*)d_in[24];
    const float* b_q      = (const float*)d_in[25];
    const float* pe       = (const float*)d_in[26];
    float* out = (float*)d_out;

    cudaFuncSetAttribute(tf_kernel, cudaFuncAttributeMaxDynamicSharedMemorySize, SMEM_BYTES);

    prep_kernel<<<256, 256>>>(tf_wqkv, tf_wo, ffn_w1, ffn_w2,
                              W_emb1, W_emb2, gat_wl, gat_wr);
    csr_build_kernel<<<1, 1024>>>(edge_idx);

    const int total_blocks = RTOT / ROWS_PER_BLK;   // 8192
    const int slice = total_blocks / 4;             // 2048
    for (int s = 0; s < 4; ++s) {
        tf_kernel<<<slice, 128, SMEM_BYTES>>>(s * slice, obs, pe,
            tf_bqkv, tf_bo, ffn_b1, ffn_b2,
            ln1_g, ln1_b, ln2_g, ln2_b,
            b_emb1, b_emb2, gat_bl, gat_br);
    }

    gat_kernel<<<(RTOT * 32) / 256, 256>>>(gat_att, gat_bias, W_q, b_q, out);
}